// round 16
// baseline (speedup 1.0000x reference)
#include <cuda_runtime.h>
#include <cuda_bf16.h>
#include <cstdint>

// Problem constants
#define TT 512
#define BB 64
#define HH 768
#define LHD 384
#define G4 1536
#define NLAB 12
#define NEGV (-1000.0f)
#define NBLK_LSTM 96

// ---------------- scratch (static device memory; no allocation) -------------
// X[dir][t][col][b], col = gate*384 + j
__device__ float g_X[100663296];
// Hseq[dir][t][j][b]
__device__ float g_Hseq[25165824];
// feats[b][t][l]
__device__ float g_feats[64 * 512 * 12];
// per-CTA step-completion flags
__device__ volatile int g_flag[NBLK_LSTM];
// bf16 split of W_ih: [dir][split(hi/lo)][1536][768]
__device__ __align__(16) __nv_bfloat16 g_Wsp[2 * 2 * 1536 * 768];
// bf16 split of hidden: [t][split][b][768]
__device__ __align__(16) __nv_bfloat16 g_Hsp[512 * 2 * 64 * 768];
// double-buffered bf16 split of recurrent h: [buf][dir][split][b][384]
__device__ __align__(16) __nv_bfloat16 g_hrec[2 * 2 * 2 * 64 * 384];

__device__ __forceinline__ float sigm(float x) {
    return 1.0f / (1.0f + __expf(-x));
}

// warp-level bf16 tensor-core MMA (sm_80+ PTX, no 'a'-suffix features)
__device__ __forceinline__ void mma_bf16(
    float& c0, float& c1, float& c2, float& c3,
    uint32_t a0, uint32_t a1, uint32_t a2, uint32_t a3,
    uint32_t b0, uint32_t b1)
{
    asm volatile(
        "mma.sync.aligned.m16n8k16.row.col.f32.bf16.bf16.f32 "
        "{%0,%1,%2,%3}, {%4,%5,%6,%7}, {%8,%9}, {%0,%1,%2,%3};"
        : "+f"(c0), "+f"(c1), "+f"(c2), "+f"(c3)
        : "r"(a0), "r"(a1), "r"(a2), "r"(a3), "r"(b0), "r"(b1));
}

__device__ __forceinline__ uint32_t smem_u32(const void* p) {
    uint32_t a;
    asm("{ .reg .u64 t; cvta.to.shared.u64 t, %1; cvt.u32.u64 %0, t; }"
        : "=r"(a) : "l"(p));
    return a;
}

__device__ __forceinline__ void ldsm_x4(uint32_t* r, uint32_t addr) {
    asm volatile("ldmatrix.sync.aligned.m8n8.x4.shared.b16 {%0,%1,%2,%3}, [%4];"
        : "=r"(r[0]), "=r"(r[1]), "=r"(r[2]), "=r"(r[3]) : "r"(addr));
}

__device__ __forceinline__ void st_release_gpu(volatile int* p, int v) {
    asm volatile("st.release.gpu.global.b32 [%0], %1;"
                 :: "l"((int*)p), "r"(v) : "memory");
}
__device__ __forceinline__ int ld_acquire_gpu(volatile int* p) {
    int v;
    asm volatile("ld.acquire.gpu.global.b32 %0, [%1];"
                 : "=r"(v) : "l"((int*)p) : "memory");
    return v;
}

// ---------------- split W + prep (flags, h0 split) ---------------------------
__global__ void __launch_bounds__(256) split_w_kernel(
    const float* __restrict__ wf, const float* __restrict__ wb,
    const float* __restrict__ h0)
{
    int tid = threadIdx.x;
    if (blockIdx.x == G4) {
        int dir = blockIdx.y;
        if (dir == 0 && tid < NBLK_LSTM) g_flag[tid] = 0;
        __nv_bfloat16* dH = g_hrec + ((size_t)(dir * 2 + 0)) * BB * LHD;
        __nv_bfloat16* dL = g_hrec + ((size_t)(dir * 2 + 1)) * BB * LHD;
        const float* src = h0 + (size_t)dir * BB * LHD;
#pragma unroll
        for (int i = 0; i < 96; i++) {
            int idx = tid + i * 256;
            float x = src[idx];
            __nv_bfloat16 hi = __float2bfloat16(x);
            __nv_bfloat16 lo = __float2bfloat16(x - __bfloat162float(hi));
            dH[idx] = hi;
            dL[idx] = lo;
        }
        return;
    }
    int col = blockIdx.x;
    int dir = blockIdx.y;
    const float* src = dir ? wb : wf;
#pragma unroll
    for (int i = 0; i < 3; i++) {
        int k = i * 256 + tid;
        float x = src[(size_t)col * HH + k];
        __nv_bfloat16 hi = __float2bfloat16(x);
        __nv_bfloat16 lo = __float2bfloat16(x - __bfloat162float(hi));
        g_Wsp[((size_t)(dir * 2 + 0) * G4 + col) * HH + k] = hi;
        g_Wsp[((size_t)(dir * 2 + 1) * G4 + col) * HH + k] = lo;
    }
}

// vectorized: 192 threads, each one float4 per batch row
__global__ void __launch_bounds__(192) split_h_kernel(
    const float* __restrict__ hid)
{
    int t = blockIdx.x;
    int b0 = blockIdx.y * 8;
    int k4 = threadIdx.x * 4;
#pragma unroll
    for (int bo = 0; bo < 8; bo++) {
        int b = b0 + bo;
        float4 v = *(const float4*)&hid[((size_t)b * TT + t) * HH + k4];
        __nv_bfloat16 h0 = __float2bfloat16(v.x);
        __nv_bfloat16 h1 = __float2bfloat16(v.y);
        __nv_bfloat16 h2 = __float2bfloat16(v.z);
        __nv_bfloat16 h3 = __float2bfloat16(v.w);
        __nv_bfloat16 l0 = __float2bfloat16(v.x - __bfloat162float(h0));
        __nv_bfloat16 l1 = __float2bfloat16(v.y - __bfloat162float(h1));
        __nv_bfloat16 l2 = __float2bfloat16(v.z - __bfloat162float(h2));
        __nv_bfloat16 l3 = __float2bfloat16(v.w - __bfloat162float(h3));
        uint2 pkH, pkL;
        pkH.x = ((uint32_t)*(uint16_t*)&h0) | ((uint32_t)*(uint16_t*)&h1 << 16);
        pkH.y = ((uint32_t)*(uint16_t*)&h2) | ((uint32_t)*(uint16_t*)&h3 << 16);
        pkL.x = ((uint32_t)*(uint16_t*)&l0) | ((uint32_t)*(uint16_t*)&l1 << 16);
        pkL.y = ((uint32_t)*(uint16_t*)&l2) | ((uint32_t)*(uint16_t*)&l3 << 16);
        *(uint2*)&g_Hsp[((size_t)(t * 2 + 0) * BB + b) * HH + k4] = pkH;
        *(uint2*)&g_Hsp[((size_t)(t * 2 + 1) * BB + b) * HH + k4] = pkL;
    }
}

// ---------------- kernel A: projection GEMM (mma.sync + ldmatrix) -----------
__global__ void __launch_bounds__(256) proj_mma_kernel(
    const float* __restrict__ bif, const float* __restrict__ bhf,
    const float* __restrict__ bib, const float* __restrict__ bhb)
{
    __shared__ __nv_bfloat16 Asm[128][40];
    __shared__ __nv_bfloat16 Bsm[128][40];

    int ct  = blockIdx.x;
    int dir = blockIdx.y;
    int tg  = blockIdx.z;
    int cb  = ct * 128;
    int t0  = tg * 2;

    int tid  = threadIdx.x;
    int lane = tid & 31;
    int warp = tid >> 5;
    int wm = (warp >> 2) * 64;
    int wn = (warp & 3) * 32;

    float acc[4][4][4];
#pragma unroll
    for (int mi = 0; mi < 4; mi++)
#pragma unroll
        for (int ni = 0; ni < 4; ni++)
#pragma unroll
            for (int q = 0; q < 4; q++) acc[mi][ni][q] = 0.0f;

    const float* b1 = dir ? bib : bif;
    const float* b2 = dir ? bhb : bhf;
    float bias0[4], bias1[4];
#pragma unroll
    for (int mi = 0; mi < 4; mi++) {
        int m0 = wm + mi * 16 + (lane >> 2);
        bias0[mi] = b1[cb + m0] + b2[cb + m0];
        bias1[mi] = b1[cb + m0 + 8] + b2[cb + m0 + 8];
    }

    // ldmatrix lane addresses (advance by ks*16 elems = 32B per ks)
    uint32_t asmBase = smem_u32(&Asm[0][0]);
    uint32_t bsmBase = smem_u32(&Bsm[0][0]);
    uint32_t aAddr[4];
#pragma unroll
    for (int mi = 0; mi < 4; mi++)
        aAddr[mi] = asmBase +
            (uint32_t)((wm + mi * 16 + (lane & 15)) * 40 + (lane >> 4) * 8) * 2;
    uint32_t bAddr[2];
#pragma unroll
    for (int nq = 0; nq < 2; nq++)
        bAddr[nq] = bsmBase +
            (uint32_t)((wn + nq * 16 + (lane & 7) + ((lane >> 4) & 1) * 8) * 40 +
                       ((lane >> 3) & 1) * 8) * 2;

    int r = tid >> 1;
    int seg = tid & 1;
    int tlL = r >> 6;
    int bbL = r & 63;

    for (int term = 0; term < 3; term++) {
        int spA = (term == 2) ? 1 : 0;
        int spB = (term == 1) ? 1 : 0;
        const __nv_bfloat16* Abase = g_Wsp +
            ((size_t)(dir * 2 + spA) * G4 + cb + r) * HH + seg * 16;
        const __nv_bfloat16* Bbase = g_Hsp +
            ((size_t)((t0 + tlL) * 2 + spB) * BB + bbL) * HH + seg * 16;

        for (int kc = 0; kc < 24; kc++) {
            uint4 av0 = *(const uint4*)(Abase + kc * 32);
            uint4 av1 = *(const uint4*)(Abase + kc * 32 + 8);
            uint4 bv0 = *(const uint4*)(Bbase + kc * 32);
            uint4 bv1 = *(const uint4*)(Bbase + kc * 32 + 8);
            __syncthreads();
            *(uint4*)&Asm[r][seg * 16]     = av0;
            *(uint4*)&Asm[r][seg * 16 + 8] = av1;
            *(uint4*)&Bsm[r][seg * 16]     = bv0;
            *(uint4*)&Bsm[r][seg * 16 + 8] = bv1;
            __syncthreads();

#pragma unroll
            for (int ks = 0; ks < 2; ks++) {
                uint32_t ko = (uint32_t)ks * 32;
                uint32_t ar[4][4], br[2][4];
#pragma unroll
                for (int mi = 0; mi < 4; mi++) ldsm_x4(ar[mi], aAddr[mi] + ko);
#pragma unroll
                for (int nq = 0; nq < 2; nq++) ldsm_x4(br[nq], bAddr[nq] + ko);
#pragma unroll
                for (int ni = 0; ni < 4; ni++) {
                    uint32_t br0 = br[ni >> 1][(ni & 1) * 2];
                    uint32_t br1 = br[ni >> 1][(ni & 1) * 2 + 1];
#pragma unroll
                    for (int mi = 0; mi < 4; mi++)
                        mma_bf16(acc[mi][ni][0], acc[mi][ni][1],
                                 acc[mi][ni][2], acc[mi][ni][3],
                                 ar[mi][0], ar[mi][1], ar[mi][2], ar[mi][3],
                                 br0, br1);
                }
            }
        }
    }

#pragma unroll
    for (int mi = 0; mi < 4; mi++) {
#pragma unroll
        for (int ni = 0; ni < 4; ni++) {
            int m0 = wm + mi * 16 + (lane >> 2);
            int n = wn + ni * 8 + (lane & 3) * 2;
            int tl = n >> 6;
            int bb = n & 63;
            float* op = g_X +
                (((size_t)dir * TT + t0 + tl) * G4 + cb) * BB;
            float2 v0, v1;
            v0.x = acc[mi][ni][0] + bias0[mi];
            v0.y = acc[mi][ni][1] + bias0[mi];
            v1.x = acc[mi][ni][2] + bias1[mi];
            v1.y = acc[mi][ni][3] + bias1[mi];
            *(float2*)&op[(size_t)m0 * BB + bb] = v0;
            *(float2*)&op[(size_t)(m0 + 8) * BB + bb] = v1;
        }
    }
}

// ---------------- kernel B: persistent BiLSTM recurrence (tensor cores) -----
#define LPAD 392
#define A_ELEMS (32 * LPAD)
#define B_ELEMS (64 * LPAD)
#define STG_PAD 68
#define LSTM_SMEM ((2 * A_ELEMS + 2 * B_ELEMS) * 2 + 8 * STG_PAD * 4)

__global__ void __launch_bounds__(256) lstm_mma_kernel(
    const float* __restrict__ c0,
    const float* __restrict__ whf, const float* __restrict__ whb)
{
    extern __shared__ __nv_bfloat16 smb[];
    __nv_bfloat16* AsmH = smb;
    __nv_bfloat16* AsmL = smb + A_ELEMS;
    __nv_bfloat16* BsmH = smb + 2 * A_ELEMS;
    __nv_bfloat16* BsmL = smb + 2 * A_ELEMS + B_ELEMS;
    float* stage = (float*)(smb + 2 * A_ELEMS + 2 * B_ELEMS);

    int tile = blockIdx.x;
    int dir = tile / 48;
    int ug = tile % 48;
    const float* W = dir ? whb : whf;

    int tid  = threadIdx.x;
    int lane = tid & 31;
    int warp = tid >> 5;

    // ---- one-time W slice preload + bf16 split
    {
        int m = tid >> 3;
        int kseg = (tid & 7) * 48;
        int wrow = (m >> 3) * LHD + ug * 8 + (m & 7);
        const float* src = W + (size_t)wrow * LHD + kseg;
#pragma unroll
        for (int i = 0; i < 48; i++) {
            float x = src[i];
            __nv_bfloat16 hi = __float2bfloat16(x);
            __nv_bfloat16 lo = __float2bfloat16(x - __bfloat162float(hi));
            AsmH[m * LPAD + kseg + i] = hi;
            AsmL[m * LPAD + kseg + i] = lo;
        }
    }

    int uloc = lane >> 2;
    int j = ug * 8 + uloc;
    int b0 = warp * 8 + (lane & 3) * 2;

    float cr0 = c0[((size_t)(dir * BB + b0)) * LHD + j];
    float cr1 = c0[((size_t)(dir * BB + b0 + 1)) * LHD + j];

    // ---- ldmatrix lane addresses
    uint32_t sb = smem_u32(smb);
    int a_r = lane & 15;
    int a_c = (lane >> 4) * 8;
    uint32_t aH_m0 = sb + (uint32_t)(a_r * LPAD + a_c) * 2;
    uint32_t aH_m1 = aH_m0 + 16 * LPAD * 2;
    uint32_t aL_m0 = aH_m0 + A_ELEMS * 2;
    uint32_t aL_m1 = aH_m1 + A_ELEMS * 2;
    // merged H/L B fragment: lanes 0-15 -> BsmH, 16-31 -> BsmL
    uint32_t bHL_ad = sb + 2 * A_ELEMS * 2 +
                      ((uint32_t)(lane >> 4)) * (B_ELEMS * 2) +
                      (uint32_t)((warp * 8 + (lane & 7)) * LPAD +
                                 ((lane >> 3) & 1) * 8) * 2;

    for (int s = 0; s < TT; s++) {
        int t = dir ? (TT - 1 - s) : s;

        // ---- prefetch x gate values (before the wait)
        float2 xv[4];
        {
            const float* xb = g_X + ((size_t)(dir * TT + t)) * G4 * BB;
#pragma unroll
            for (int g = 0; g < 4; g++)
                xv[g] = *(const float2*)&xb[((size_t)g * LHD + j) * BB + b0];
        }

        // ---- wait for previous step of this direction (acquire)
        if (s > 0) {
            if (tid < 48) {
                while (ld_acquire_gpu(&g_flag[dir * 48 + tid]) < s) { }
            }
        }
        __syncthreads();

        // ---- load B = h split [64][384] hi+lo from g_hrec buf (s&1)
        {
            int rb = s & 1;
            const __nv_bfloat16* srcH = g_hrec +
                ((size_t)((rb * 2 + dir) * 2 + 0)) * BB * LHD;
            const __nv_bfloat16* srcL = g_hrec +
                ((size_t)((rb * 2 + dir) * 2 + 1)) * BB * LHD;
#pragma unroll
            for (int i = 0; i < 12; i++) {
                int u = tid + i * 256;
                int row = u / 48;
                int c16 = u % 48;
                uint4 v = *(const uint4*)(srcH + (size_t)row * LHD + c16 * 8);
                *(uint4*)&BsmH[row * LPAD + c16 * 8] = v;
            }
#pragma unroll
            for (int i = 0; i < 12; i++) {
                int u = tid + i * 256;
                int row = u / 48;
                int c16 = u % 48;
                uint4 v = *(const uint4*)(srcL + (size_t)row * LHD + c16 * 8);
                *(uint4*)&BsmL[row * LPAD + c16 * 8] = v;
            }
        }
        __syncthreads();

        // ---- MMA via ldmatrix: 3 split terms, K=384
        float acc0[4] = {0.f, 0.f, 0.f, 0.f};
        float acc1[4] = {0.f, 0.f, 0.f, 0.f};

#pragma unroll 6
        for (int kc = 0; kc < 24; kc++) {
            uint32_t ko = (uint32_t)kc * 32;
            uint32_t aH0[4], aH1[4], aL0[4], aL1[4], bHL[4];
            ldsm_x4(aH0, aH_m0 + ko);
            ldsm_x4(aH1, aH_m1 + ko);
            ldsm_x4(bHL, bHL_ad + ko);
            ldsm_x4(aL0, aL_m0 + ko);
            ldsm_x4(aL1, aL_m1 + ko);
            mma_bf16(acc0[0], acc0[1], acc0[2], acc0[3],
                     aH0[0], aH0[1], aH0[2], aH0[3], bHL[0], bHL[1]);
            mma_bf16(acc1[0], acc1[1], acc1[2], acc1[3],
                     aH1[0], aH1[1], aH1[2], aH1[3], bHL[0], bHL[1]);
            mma_bf16(acc0[0], acc0[1], acc0[2], acc0[3],
                     aH0[0], aH0[1], aH0[2], aH0[3], bHL[2], bHL[3]);
            mma_bf16(acc1[0], acc1[1], acc1[2], acc1[3],
                     aH1[0], aH1[1], aH1[2], aH1[3], bHL[2], bHL[3]);
            mma_bf16(acc0[0], acc0[1], acc0[2], acc0[3],
                     aL0[0], aL0[1], aL0[2], aL0[3], bHL[0], bHL[1]);
            mma_bf16(acc1[0], acc1[1], acc1[2], acc1[3],
                     aL1[0], aL1[1], aL1[2], aL1[3], bHL[0], bHL[1]);
        }

        // ---- gate nonlinearities
        float h0v, h1v;
        {
            float gi = acc0[0] + xv[0].x;
            float gf = acc0[2] + xv[1].x;
            float gg = acc1[0] + xv[2].x;
            float go = acc1[2] + xv[3].x;
            cr0 = sigm(gf) * cr0 + sigm(gi) * tanhf(gg);
            h0v = sigm(go) * tanhf(cr0);
        }
        {
            float gi = acc0[1] + xv[0].y;
            float gf = acc0[3] + xv[1].y;
            float gg = acc1[1] + xv[2].y;
            float go = acc1[3] + xv[3].y;
            cr1 = sigm(gf) * cr1 + sigm(gi) * tanhf(cr1 * 0.0f + gg);
            h1v = sigm(go) * tanhf(cr1);
        }

        // ---- stage h in smem, then coalesced writeout
        stage[uloc * STG_PAD + b0]     = h0v;
        stage[uloc * STG_PAD + b0 + 1] = h1v;
        __syncthreads();

        {
            int v = tid * 2;
            int jl = v >> 6;
            int bb = v & 63;
            float2 hv = make_float2(stage[jl * STG_PAD + bb],
                                    stage[jl * STG_PAD + bb + 1]);
            *(float2*)&g_Hseq[(((size_t)dir * TT + t) * LHD + ug * 8 + jl) * BB + bb] = hv;

            int wbuf = (s + 1) & 1;
            __nv_bfloat16* dstH = g_hrec +
                ((size_t)((wbuf * 2 + dir) * 2 + 0)) * BB * LHD;
            __nv_bfloat16* dstL = g_hrec +
                ((size_t)((wbuf * 2 + dir) * 2 + 1)) * BB * LHD;
            int bb2 = tid >> 2;
            int pr  = (tid & 3) * 2;
            float v0 = stage[pr * STG_PAD + bb2];
            float v1 = stage[(pr + 1) * STG_PAD + bb2];
            __nv_bfloat16 h0b = __float2bfloat16(v0);
            __nv_bfloat16 h1b = __float2bfloat16(v1);
            __nv_bfloat16 l0b = __float2bfloat16(v0 - __bfloat162float(h0b));
            __nv_bfloat16 l1b = __float2bfloat16(v1 - __bfloat162float(h1b));
            uint32_t packH = ((uint32_t)*(uint16_t*)&h0b) |
                             ((uint32_t)*(uint16_t*)&h1b << 16);
            uint32_t packL = ((uint32_t)*(uint16_t*)&l0b) |
                             ((uint32_t)*(uint16_t*)&l1b << 16);
            *(uint32_t*)&dstH[(size_t)bb2 * LHD + ug * 8 + pr] = packH;
            *(uint32_t*)&dstL[(size_t)bb2 * LHD + ug * 8 + pr] = packL;
        }

        // ---- release: ensure all CTA stores precede the flag publish
        __syncthreads();
        if (tid == 0) st_release_gpu(&g_flag[tile], s + 1);
    }
}

// ---------------- kernel C: FC emissions -------------------------------------
__global__ void __launch_bounds__(256) fc_kernel(
    const float* __restrict__ fcw, const float* __restrict__ fcb)
{
    __shared__ float Wsm[NLAB * 768];
    __shared__ float Bsm[NLAB];

    int t = blockIdx.x;
    int tid = threadIdx.x;
    for (int i = tid; i < NLAB * 768; i += 256) Wsm[i] = fcw[i];
    if (tid < NLAB) Bsm[tid] = fcb[tid];
    __syncthreads();

    int b = tid & 63;
    int lg = tid >> 6;
    float acc[3];
#pragma unroll
    for (int q = 0; q < 3; q++) acc[q] = Bsm[lg * 3 + q];

    const float* hf = g_Hseq + ((size_t)0 * TT + t) * LHD * BB;
    const float* hb = g_Hseq + ((size_t)1 * TT + t) * LHD * BB;
    for (int j = 0; j < LHD; j++) {
        float vf = hf[j * BB + b];
        float vb = hb[j * BB + b];
#pragma unroll
        for (int q = 0; q < 3; q++) {
            int l = lg * 3 + q;
            acc[q] += vf * Wsm[l * 768 + j] + vb * Wsm[l * 768 + LHD + j];
        }
    }
#pragma unroll
    for (int q = 0; q < 3; q++)
        g_feats[((size_t)b * TT + t) * NLAB + lg * 3 + q] = acc[q];
}

// ---------------- kernel D: Viterbi ------------------------------------------
__global__ void __launch_bounds__(128) viterbi_kernel(
    const float* __restrict__ trans, const int* __restrict__ start_ptr,
    float* __restrict__ out)
{
    __shared__ float sf[TT * NLAB];
    __shared__ float ts[NLAB * NLAB];
    __shared__ float fv[NLAB];
    __shared__ unsigned char ptr[TT * NLAB];

    int b = blockIdx.x;
    int tid = threadIdx.x;
    for (int i = tid; i < TT * NLAB; i += 128) sf[i] = g_feats[(size_t)b * TT * NLAB + i];
    for (int i = tid; i < NLAB * NLAB; i += 128) ts[i] = trans[i];
    int start = *start_ptr;
    if (tid < NLAB) fv[tid] = (tid == start) ? 0.0f : NEGV;
    __syncthreads();

    if (tid < 32) {
        for (int t = 1; t < TT; t++) {
            float best = 0.0f; int arg = 0;
            if (tid < NLAB) {
                best = ts[tid * NLAB + 0] + fv[0]; arg = 0;
#pragma unroll
                for (int p = 1; p < NLAB; p++) {
                    float v = ts[tid * NLAB + p] + fv[p];
                    if (v > best) { best = v; arg = p; }
                }
                best += sf[t * NLAB + tid];
            }
            __syncwarp();
            if (tid < NLAB) {
                fv[tid] = best;
                ptr[t * NLAB + tid] = (unsigned char)arg;
            }
            __syncwarp();
        }
        if (tid == 0) {
            float bs = fv[0]; int last = 0;
            for (int l = 1; l < NLAB; l++)
                if (fv[l] > bs) { bs = fv[l]; last = l; }
            out[b] = bs;
            float* pp = out + 64 + (size_t)b * TT;
            int cur = last;
            pp[TT - 1] = (float)cur;
            for (int t = TT - 2; t >= 0; t--) {
                cur = ptr[(t + 1) * NLAB + cur];
                pp[t] = (float)cur;
            }
        }
    }
}

// ---------------- launch ------------------------------------------------------
extern "C" void kernel_launch(void* const* d_in, const int* in_sizes, int n_in,
                              void* d_out, int out_size)
{
    const float* hidden = (const float*)d_in[0];
    const float* h0     = (const float*)d_in[1];
    const float* c0     = (const float*)d_in[2];
    const float* w_ih_f = (const float*)d_in[3];
    const float* w_hh_f = (const float*)d_in[4];
    const float* b_ih_f = (const float*)d_in[5];
    const float* b_hh_f = (const float*)d_in[6];
    const float* w_ih_b = (const float*)d_in[7];
    const float* w_hh_b = (const float*)d_in[8];
    const float* b_ih_b = (const float*)d_in[9];
    const float* b_hh_b = (const float*)d_in[10];
    const float* fc_w   = (const float*)d_in[11];
    const float* fc_b   = (const float*)d_in[12];
    const float* transitions = (const float*)d_in[13];
    const int*   start_idx   = (const int*)d_in[14];

    static int attr_set = 0;
    if (!attr_set) {
        cudaFuncSetAttribute(lstm_mma_kernel,
                             cudaFuncAttributeMaxDynamicSharedMemorySize,
                             LSTM_SMEM);
        attr_set = 1;
    }

    split_w_kernel<<<dim3(G4 + 1, 2), 256>>>(w_ih_f, w_ih_b, h0);
    split_h_kernel<<<dim3(512, 8), 192>>>(hidden);
    proj_mma_kernel<<<dim3(12, 2, 256), 256>>>(b_ih_f, b_hh_f,
                                                b_ih_b, b_hh_b);
    lstm_mma_kernel<<<NBLK_LSTM, 256, LSTM_SMEM>>>(c0, w_hh_f, w_hh_b);
    fc_kernel<<<512, 256>>>(fc_w, fc_b);
    viterbi_kernel<<<64, 128>>>(transitions, start_idx, (float*)d_out);
}